// round 16
// baseline (speedup 1.0000x reference)
#include <cuda_runtime.h>
#include <cstdint>
#include <cfloat>

#define FULL_MASK 0xFFFFFFFFu

static constexpr int M = 512;           // factors per token
static constexpr int KSEL = 8;          // top-k
static constexpr int WARPS_PER_BLOCK = 8;
static constexpr int THREADS = WARPS_PER_BLOCK * 32;

// Monotone float -> uint32 (order-preserving), and inverse.
__device__ __forceinline__ unsigned f2ord(float f) {
    unsigned u = __float_as_uint(f);
    return u ^ ((unsigned)(((int)u) >> 31) | 0x80000000u);
}
__device__ __forceinline__ float ord2f(unsigned o) {
    unsigned u = o ^ ((o & 0x80000000u) ? 0x80000000u : 0xFFFFFFFFu);
    return __uint_as_float(u);
}
__device__ __forceinline__ float ex2(float x) {
    float r;
    asm("ex2.approx.ftz.f32 %0, %1;" : "=f"(r) : "f"(x));
    return r;
}

// 256-bit global load/store (sm_100a+: LDG.256 / STG.256), streaming policy.
__device__ __forceinline__ void ldg256_cs(const float* p, float* v) {
    asm volatile("ld.global.cs.v8.f32 {%0,%1,%2,%3,%4,%5,%6,%7}, [%8];"
                 : "=f"(v[0]), "=f"(v[1]), "=f"(v[2]), "=f"(v[3]),
                   "=f"(v[4]), "=f"(v[5]), "=f"(v[6]), "=f"(v[7])
                 : "l"(p));
}
__device__ __forceinline__ void stg256_cs(float* p, const float* v) {
    asm volatile("st.global.cs.v8.f32 [%0], {%1,%2,%3,%4,%5,%6,%7,%8};"
                 :: "l"(p),
                    "f"(v[0]), "f"(v[1]), "f"(v[2]), "f"(v[3]),
                    "f"(v[4]), "f"(v[5]), "f"(v[6]), "f"(v[7])
                 : "memory");
}

// One warp per row. Lane owns 16 cols in two 8-wide chunks:
//   slot t = j*8 + k  <->  col = j*256 + lane*8 + k   (j in {0,1}, k in {0..7})
// All selection math happens in the log2-scaled domain: adj2 = (logit-beta)*log2e.
__global__ void __launch_bounds__(THREADS) qb_gating_kernel(
    const float* __restrict__ logits,
    const float* __restrict__ beta,
    float* __restrict__ out,
    int nrows)
{
    __shared__ float s_b2[M];      // beta * log2(e)
    __shared__ float s_ebeta[M];   // exp(beta)
    const float LOG2E = 1.4426950408889634f;
    for (int i = threadIdx.x; i < M; i += THREADS) {
        float b = beta[i];
        s_b2[i]    = b * LOG2E;
        s_ebeta[i] = __expf(b);
    }
    __syncthreads();

    const int lane = threadIdx.x & 31;
    const int warp = threadIdx.x >> 5;
    const int row = blockIdx.x * WARPS_PER_BLOCK + warp;
    if (row >= nrows) return;

    const float* rp = logits + (size_t)row * M;
    const float NEG_INF = __int_as_float(0xff800000);

    // ---- load (2x 256-bit) + debias into exp2 domain ----
    float adj[16];
#pragma unroll
    for (int j = 0; j < 2; ++j) {
        float v[8];
        ldg256_cs(rp + j * 256 + lane * 8, v);
        const float* b = &s_b2[j * 256 + lane * 8];
#pragma unroll
        for (int k = 0; k < 8; ++k)
            adj[j * 8 + k] = fmaf(v[k], LOG2E, -b[k]);
    }

    // ---- per-lane top-3 via sorted-merge tournament (multiset-correct) ----
    float m1, m2, m3;
    {
        float p1[8], p2[8];
#pragma unroll
        for (int i = 0; i < 8; ++i) {
            p1[i] = fmaxf(adj[2 * i], adj[2 * i + 1]);
            p2[i] = fminf(adj[2 * i], adj[2 * i + 1]);
        }
        float q1[4], q2[4], q3[4];
#pragma unroll
        for (int i = 0; i < 4; ++i) {
            float a1 = p1[2 * i], a2 = p2[2 * i];
            float b1 = p1[2 * i + 1], b2 = p2[2 * i + 1];
            float c1 = fmaxf(a1, b1), d1 = fminf(a1, b1);
            float c2 = fmaxf(a2, b2), d2 = fminf(a2, b2);
            q1[i] = c1;
            q2[i] = fmaxf(d1, c2);
            q3[i] = fmaxf(fminf(d1, c2), d2);
        }
        float r1[2], r2[2], r3[2];
#pragma unroll
        for (int i = 0; i < 2; ++i) {
            float a1 = q1[2 * i], a2 = q2[2 * i], a3 = q3[2 * i];
            float b1 = q1[2 * i + 1], b2 = q2[2 * i + 1], b3 = q3[2 * i + 1];
            float x = fminf(a1, b1), y = fmaxf(a2, b2);
            r1[i] = fmaxf(a1, b1);
            r2[i] = fmaxf(x, y);
            r3[i] = fmaxf(fminf(x, y), fmaxf(fminf(a2, b2), fmaxf(a3, b3)));
        }
        {
            float a1 = r1[0], a2 = r2[0], a3 = r3[0];
            float b1 = r1[1], b2 = r2[1], b3 = r3[1];
            float x = fminf(a1, b1), y = fmaxf(a2, b2);
            m1 = fmaxf(a1, b1);
            m2 = fmaxf(x, y);
            m3 = fmaxf(fminf(x, y), fmaxf(fminf(a2, b2), fmaxf(a3, b3)));
        }
    }

    // ---- 8 extraction rounds over the 96-candidate pool ----
    unsigned cur = f2ord(m1), c1 = f2ord(m2), c2 = f2ord(m3);
    unsigned thr = 0, c_ord = 0;
#pragma unroll
    for (int it = 0; it < KSEL; ++it) {
        unsigned wmax = __reduce_max_sync(FULL_MASK, cur);
        if (it == 0) c_ord = wmax;     // global max: free softmax stabilizer
        bool eq = (cur == wmax);
        cur = eq ? c1 : cur;
        c1  = eq ? c2 : c1;
        c2  = eq ? 0u : c2;
        thr = wmax;
    }

    // ---- validate threshold: exactly 8 elements >= thr -> exact top-8 set ----
    float thr_f = ord2f(thr);
    int cnt = 0;
#pragma unroll
    for (int t = 0; t < 16; ++t)
        cnt += (adj[t] >= thr_f) ? 1 : 0;
    int n_sel = __reduce_add_sync(FULL_MASK, cnt);

    if (n_sel != KSEL) {
        // EXACT fallback (rare): index-tracked extraction, lower-column
        // tie-break (bit-matches jax.lax.top_k). Mapping:
        //   col = (t>>3)*256 + lane*8 + (t&7)
        unsigned used = 0;
        for (int it = 0; it < KSEL; ++it) {
            float best = NEG_INF;
            int bs = 0;
#pragma unroll
            for (int t = 0; t < 16; ++t) {
                bool ok = !((used >> t) & 1u) && (adj[t] > best);
                best = ok ? adj[t] : best;
                bs = ok ? t : bs;
            }
            int bcol = ((bs >> 3) << 8) | (lane << 3) | (bs & 7);
#pragma unroll
            for (int off = 16; off > 0; off >>= 1) {
                float ov = __shfl_down_sync(FULL_MASK, best, off);
                int   oc = __shfl_down_sync(FULL_MASK, bcol, off);
                if (ov > best || (ov == best && oc < bcol)) { best = ov; bcol = oc; }
            }
            bcol = __shfl_sync(FULL_MASK, bcol, 0);
            if (lane == ((bcol >> 3) & 31))
                used |= 1u << (((bcol >> 8) << 3) | (bcol & 7));
        }
#pragma unroll
        for (int t = 0; t < 16; ++t)
            if (!((used >> t) & 1u)) adj[t] = NEG_INF;
        thr_f = -FLT_MAX;
    }

    // ---- masked softmax in one pass: me = sel ? exp2(adj-c)*e^beta : 0 ----
    float c_f = ord2f(c_ord);
    float s = 0.f;
#pragma unroll
    for (int j = 0; j < 2; ++j) {
        const float* eb = &s_ebeta[j * 256 + lane * 8];
#pragma unroll
        for (int k = 0; k < 8; ++k) {
            int t = j * 8 + k;
            bool sel = (adj[t] >= thr_f);
            float e = ex2(adj[t] - c_f) * eb[k];
            float me = sel ? e : 0.f;
            adj[t] = me;
            s += me;
        }
    }
#pragma unroll
    for (int off = 16; off > 0; off >>= 1)
        s += __shfl_xor_sync(FULL_MASK, s, off);
    float inv = __fdividef(1.f, s);

    // ---- store full row (2x 256-bit streaming stores) ----
    float* orow = out + (size_t)row * M;
#pragma unroll
    for (int j = 0; j < 2; ++j) {
        float o[8];
#pragma unroll
        for (int k = 0; k < 8; ++k)
            o[k] = adj[j * 8 + k] * inv;
        stg256_cs(orow + j * 256 + lane * 8, o);
    }
}

extern "C" void kernel_launch(void* const* d_in, const int* in_sizes, int n_in,
                              void* d_out, int out_size) {
    const float* logits = (const float*)d_in[0];
    const float* beta   = (const float*)d_in[1];
    float* out          = (float*)d_out;
    int nrows = in_sizes[0] / M;
    int blocks = (nrows + WARPS_PER_BLOCK - 1) / WARPS_PER_BLOCK;
    qb_gating_kernel<<<blocks, THREADS>>>(logits, beta, out, nrows);
}

// round 17
// speedup vs baseline: 1.0004x; 1.0004x over previous
#include <cuda_runtime.h>
#include <cstdint>
#include <cfloat>

#define FULL_MASK 0xFFFFFFFFu

static constexpr int M = 512;           // factors per token
static constexpr int KSEL = 8;          // top-k
static constexpr int WARPS_PER_BLOCK = 8;
static constexpr int THREADS = WARPS_PER_BLOCK * 32;

// Monotone float -> uint32 (order-preserving), and inverse.
__device__ __forceinline__ unsigned f2ord(float f) {
    unsigned u = __float_as_uint(f);
    return u ^ ((unsigned)(((int)u) >> 31) | 0x80000000u);
}
__device__ __forceinline__ float ord2f(unsigned o) {
    unsigned u = o ^ ((o & 0x80000000u) ? 0x80000000u : 0xFFFFFFFFu);
    return __uint_as_float(u);
}
__device__ __forceinline__ float ex2(float x) {
    float r;
    asm("ex2.approx.ftz.f32 %0, %1;" : "=f"(r) : "f"(x));
    return r;
}

// One warp per row. Lane owns 16 cols: slot t=4j+k <-> col = j*128 + lane*4 + k.
// All selection math happens in the log2-scaled domain: adj2 = (logit-beta)*log2e.
__global__ void __launch_bounds__(THREADS) qb_gating_kernel(
    const float* __restrict__ logits,
    const float* __restrict__ beta,
    float* __restrict__ out,
    int nrows)
{
    __shared__ float s_b2[M];      // beta * log2(e)
    __shared__ float s_ebeta[M];   // exp(beta)
    const float LOG2E = 1.4426950408889634f;
    for (int i = threadIdx.x; i < M; i += THREADS) {
        float b = beta[i];
        s_b2[i]    = b * LOG2E;
        s_ebeta[i] = __expf(b);
    }
    __syncthreads();

    const int lane = threadIdx.x & 31;
    const int warp = threadIdx.x >> 5;
    const int row = blockIdx.x * WARPS_PER_BLOCK + warp;
    if (row >= nrows) return;

    const float4* rp  = reinterpret_cast<const float4*>(logits) + (size_t)row * (M / 4);
    const float4* sb4 = reinterpret_cast<const float4*>(s_b2);
    const float4* se4 = reinterpret_cast<const float4*>(s_ebeta);

    const float NEG_INF = __int_as_float(0xff800000);

    // ---- load + debias into exp2 domain: adj2 = v*log2e - beta*log2e ----
    float adj[16];
#pragma unroll
    for (int j = 0; j < 4; ++j) {
        float4 v = __ldcs(rp + j * 32 + lane);
        float4 b = sb4[j * 32 + lane];
        adj[4 * j + 0] = fmaf(v.x, LOG2E, -b.x);
        adj[4 * j + 1] = fmaf(v.y, LOG2E, -b.y);
        adj[4 * j + 2] = fmaf(v.z, LOG2E, -b.z);
        adj[4 * j + 3] = fmaf(v.w, LOG2E, -b.w);
    }

    // ---- per-lane top-3 via sorted-merge tournament (multiset-correct) ----
    float m1, m2, m3;
    {
        float p1[8], p2[8];
#pragma unroll
        for (int i = 0; i < 8; ++i) {
            p1[i] = fmaxf(adj[2 * i], adj[2 * i + 1]);
            p2[i] = fminf(adj[2 * i], adj[2 * i + 1]);
        }
        float q1[4], q2[4], q3[4];
#pragma unroll
        for (int i = 0; i < 4; ++i) {
            float a1 = p1[2 * i], a2 = p2[2 * i];
            float b1 = p1[2 * i + 1], b2 = p2[2 * i + 1];
            float c1 = fmaxf(a1, b1), d1 = fminf(a1, b1);
            float c2 = fmaxf(a2, b2), d2 = fminf(a2, b2);
            q1[i] = c1;
            q2[i] = fmaxf(d1, c2);
            q3[i] = fmaxf(fminf(d1, c2), d2);
        }
        float r1[2], r2[2], r3[2];
#pragma unroll
        for (int i = 0; i < 2; ++i) {
            float a1 = q1[2 * i], a2 = q2[2 * i], a3 = q3[2 * i];
            float b1 = q1[2 * i + 1], b2 = q2[2 * i + 1], b3 = q3[2 * i + 1];
            float x = fminf(a1, b1), y = fmaxf(a2, b2);
            r1[i] = fmaxf(a1, b1);
            r2[i] = fmaxf(x, y);
            r3[i] = fmaxf(fminf(x, y), fmaxf(fminf(a2, b2), fmaxf(a3, b3)));
        }
        {
            float a1 = r1[0], a2 = r2[0], a3 = r3[0];
            float b1 = r1[1], b2 = r2[1], b3 = r3[1];
            float x = fminf(a1, b1), y = fmaxf(a2, b2);
            m1 = fmaxf(a1, b1);
            m2 = fmaxf(x, y);
            m3 = fmaxf(fminf(x, y), fmaxf(fminf(a2, b2), fmaxf(a3, b3)));
        }
    }

    // ---- 8 extraction rounds over the 96-candidate pool ----
    unsigned cur = f2ord(m1), c1 = f2ord(m2), c2 = f2ord(m3);
    unsigned thr = 0, c_ord = 0;
#pragma unroll
    for (int it = 0; it < KSEL; ++it) {
        unsigned wmax = __reduce_max_sync(FULL_MASK, cur);
        if (it == 0) c_ord = wmax;     // global max: free softmax stabilizer
        bool eq = (cur == wmax);
        cur = eq ? c1 : cur;
        c1  = eq ? c2 : c1;
        c2  = eq ? 0u : c2;
        thr = wmax;
    }

    // ---- validate threshold: exactly 8 elements >= thr -> exact top-8 set ----
    float thr_f = ord2f(thr);
    int cnt = 0;
#pragma unroll
    for (int t = 0; t < 16; ++t)
        cnt += (adj[t] >= thr_f) ? 1 : 0;
    int n_sel = __reduce_add_sync(FULL_MASK, cnt);

    if (n_sel != KSEL) {
        // EXACT fallback (rare): index-tracked extraction, lower-column
        // tie-break (bit-matches jax.lax.top_k).
        unsigned used = 0;
        for (int it = 0; it < KSEL; ++it) {
            float best = NEG_INF;
            int bs = 0;
#pragma unroll
            for (int t = 0; t < 16; ++t) {
                bool ok = !((used >> t) & 1u) && (adj[t] > best);
                best = ok ? adj[t] : best;
                bs = ok ? t : bs;
            }
            int bcol = ((bs >> 2) << 7) | (lane << 2) | (bs & 3);
#pragma unroll
            for (int off = 16; off > 0; off >>= 1) {
                float ov = __shfl_down_sync(FULL_MASK, best, off);
                int   oc = __shfl_down_sync(FULL_MASK, bcol, off);
                if (ov > best || (ov == best && oc < bcol)) { best = ov; bcol = oc; }
            }
            bcol = __shfl_sync(FULL_MASK, bcol, 0);
            if (lane == ((bcol >> 2) & 31))
                used |= 1u << (((bcol >> 7) << 2) | (bcol & 3));
        }
#pragma unroll
        for (int t = 0; t < 16; ++t)
            if (!((used >> t) & 1u)) adj[t] = NEG_INF;
        thr_f = -FLT_MAX;
    }

    // ---- masked softmax in one pass: me = sel ? exp2(adj-c)*e^beta : 0 ----
    float c_f = ord2f(c_ord);
    float s = 0.f;
#pragma unroll
    for (int j = 0; j < 4; ++j) {
        float4 eb = se4[j * 32 + lane];
        const float* ep = &eb.x;
#pragma unroll
        for (int k = 0; k < 4; ++k) {
            int t = 4 * j + k;
            bool sel = (adj[t] >= thr_f);
            float e = ex2(adj[t] - c_f) * ep[k];
            float me = sel ? e : 0.f;
            adj[t] = me;
            s += me;
        }
    }
#pragma unroll
    for (int off = 16; off > 0; off >>= 1)
        s += __shfl_xor_sync(FULL_MASK, s, off);
    float inv = __fdividef(1.f, s);

    // ---- store full row (dense 16B streaming stores: optimal write pattern) ----
    float4* op = reinterpret_cast<float4*>(out) + (size_t)row * (M / 4);
#pragma unroll
    for (int j = 0; j < 4; ++j) {
        float4 o;
        o.x = adj[4 * j + 0] * inv;
        o.y = adj[4 * j + 1] * inv;
        o.z = adj[4 * j + 2] * inv;
        o.w = adj[4 * j + 3] * inv;
        __stcs(op + j * 32 + lane, o);
    }
}

extern "C" void kernel_launch(void* const* d_in, const int* in_sizes, int n_in,
                              void* d_out, int out_size) {
    const float* logits = (const float*)d_in[0];
    const float* beta   = (const float*)d_in[1];
    float* out          = (float*)d_out;
    int nrows = in_sizes[0] / M;
    int blocks = (nrows + WARPS_PER_BLOCK - 1) / WARPS_PER_BLOCK;
    qb_gating_kernel<<<blocks, THREADS>>>(logits, beta, out, nrows);
}